// round 5
// baseline (speedup 1.0000x reference)
#include <cuda_runtime.h>

// DiarizationLoss: B=32, T=65536, S=4, scalar output. Persistent fused kernel.

#define NB 32
#define NT 65536
#define CEPS 1e-7f

#define CHUNKS_PER_B 64
#define TOTAL_CHUNKS (NB * CHUNKS_PER_B)   // 2048
#define CHUNK_T (NT / CHUNKS_PER_B)        // 1024
#define THREADS 256
#define ITERS (CHUNK_T / THREADS)          // 4
#define GRID 608                           // 4 blocks/SM x 152 SMs: one wave

__device__ float g_part[NB][21];
__device__ unsigned int g_count;

__global__ __launch_bounds__(THREADS, 4) void diar_loss_kernel(
    const float* __restrict__ ps,
    const float* __restrict__ pv,
    const float* __restrict__ lb,
    const float* __restrict__ vad,
    const int*   __restrict__ len32,
    float*       __restrict__ out)
{
    // lengths dtype probe (values in [32768,65536), nonzero):
    // int64 LE => word1 (hi of lengths[0]) == 0 ; int32 => word1 >= 32768.
    __shared__ int s_len[NB];
    if (threadIdx.x < NB) {
        const bool is64 = (len32[1] == 0);
        s_len[threadIdx.x] = is64 ? len32[2 * threadIdx.x] : len32[threadIdx.x];
    }
    __syncthreads();

    float acc[21];
    #pragma unroll
    for (int k = 0; k < 21; k++) acc[k] = 0.0f;
    // per-batch weighted accumulation is NOT possible across batches in one
    // register set, so accumulate per (batch-local) chunk and flush per batch
    // change. Simpler: accumulate separately and atomically flush per chunk's
    // batch. To keep one flush per block, note each block visits chunks of
    // ascending c; batches interleave. Instead keep 21 accs tagged by batch:
    // flush whenever batch changes, final flush at end.
    int cur_b = -1;

    auto flush = [&](int bb) {
        // block reduction: warp shuffle -> shared -> one RED per value
        __shared__ float sm[21][8];
        const int lane = threadIdx.x & 31;
        const int w    = threadIdx.x >> 5;
        #pragma unroll
        for (int k = 0; k < 21; k++) {
            float v = acc[k];
            v += __shfl_down_sync(0xffffffffu, v, 16);
            v += __shfl_down_sync(0xffffffffu, v, 8);
            v += __shfl_down_sync(0xffffffffu, v, 4);
            v += __shfl_down_sync(0xffffffffu, v, 2);
            v += __shfl_down_sync(0xffffffffu, v, 1);
            if (lane == 0) sm[k][w] = v;
            acc[k] = 0.0f;
        }
        __syncthreads();
        if (threadIdx.x < 21) {
            float v = 0.0f;
            #pragma unroll
            for (int ww = 0; ww < 8; ww++) v += sm[threadIdx.x][ww];
            atomicAdd(&g_part[bb][threadIdx.x], v);
        }
        __syncthreads();
    };

    for (int c = blockIdx.x; c < TOTAL_CHUNKS; c += GRID) {
        const int b     = c >> 6;            // c / CHUNKS_PER_B
        const int chunk = c & 63;
        const int len   = s_len[b];
        const int t0    = chunk * CHUNK_T;
        if (t0 >= len) continue;             // block-uniform skip

        if (cur_b != b) {
            if (cur_b >= 0) flush(cur_b);
            cur_b = b;
        }

        const float4* __restrict__ psb = (const float4*)(ps + (size_t)b * NT * 4);
        const float4* __restrict__ lbb = (const float4*)(lb + (size_t)b * NT * 4);
        const float*  __restrict__ pvb = pv  + (size_t)b * NT;
        const float*  __restrict__ vb  = vad + (size_t)b * NT;

        auto compute = [&](float4 p4, float4 l4, float pvv, float v) {
            float pp[4] = {p4.x, p4.y, p4.z, p4.w};
            float ll[4] = {l4.x, l4.y, l4.z, l4.w};
            float d[4];
            #pragma unroll
            for (int i = 0; i < 4; i++) {
                float p  = fminf(fmaxf(pp[i], CEPS), 1.0f - CEPS);
                float lq = __logf(1.0f - p);
                float lp = __logf(p);
                d[i] = lp - lq;
                acc[16 + i] += lq;
            }
            #pragma unroll
            for (int i = 0; i < 4; i++)
                #pragma unroll
                for (int j = 0; j < 4; j++)
                    acc[i * 4 + j] += d[i] * ll[j];
            pvv = fminf(fmaxf(pvv, CEPS), 1.0f - CEPS);
            float arg = (v > 0.5f) ? pvv : (1.0f - pvv);
            acc[20] -= __logf(arg);
        };

        if (t0 + CHUNK_T <= len) {
            // full chunk: software-pipelined loads (depth 2)
            int t = t0 + threadIdx.x;
            float4 pc = psb[t], lc = lbb[t];
            float pvc = pvb[t], vc = vb[t];
            #pragma unroll
            for (int it = 0; it < ITERS; it++) {
                float4 pn, ln; float pvn, vn;
                if (it + 1 < ITERS) {
                    int tn = t + THREADS;
                    pn = psb[tn]; ln = lbb[tn];
                    pvn = pvb[tn]; vn = vb[tn];
                }
                compute(pc, lc, pvc, vc);
                pc = pn; lc = ln; pvc = pvn; vc = vn;
                t += THREADS;
            }
        } else {
            for (int t = t0 + threadIdx.x; t < len; t += THREADS)
                compute(psb[t], lbb[t], pvb[t], vb[t]);
        }
    }
    if (cur_b >= 0) flush(cur_b);

    // ---- last-block finalize ----
    __shared__ int s_last;
    if (threadIdx.x == 0) {
        __threadfence();
        unsigned prev = atomicAdd(&g_count, 1u);
        s_last = (prev == (unsigned)(GRID - 1));
    }
    __syncthreads();
    if (!s_last) return;
    __threadfence();

    if (threadIdx.x < NB) {
        const int bb = threadIdx.x;
        const float msum = (float)s_len[bb];
        const float inv  = 1.0f / msum;

        float L[4][4];
        #pragma unroll
        for (int i = 0; i < 4; i++)
            #pragma unroll
            for (int j = 0; j < 4; j++)
                L[i][j] = -(g_part[bb][i * 4 + j] + g_part[bb][16 + i]) * inv;

        float best = 3.4e38f;
        #pragma unroll
        for (int a = 0; a < 4; a++)
            #pragma unroll
            for (int cc = 0; cc < 4; cc++) {
                if (cc == a) continue;
                #pragma unroll
                for (int e = 0; e < 4; e++) {
                    if (e == a || e == cc) continue;
                    int f = 6 - a - cc - e;
                    best = fminf(best, L[0][a] + L[1][cc] + L[2][e] + L[3][f]);
                }
            }
        best *= 0.25f;

        float sb = best, sv = g_part[bb][20], sd = msum;
        #pragma unroll
        for (int off = 16; off >= 1; off >>= 1) {
            sb += __shfl_xor_sync(0xffffffffu, sb, off);
            sv += __shfl_xor_sync(0xffffffffu, sv, off);
            sd += __shfl_xor_sync(0xffffffffu, sd, off);
        }
        if (bb == 0)
            out[0] = (sb / (float)NB) + 0.5f * (sv / sd);
    }
    __syncthreads();

    // reset scratch for next graph replay
    for (int i = threadIdx.x; i < NB * 21; i += THREADS)
        ((float*)g_part)[i] = 0.0f;
    if (threadIdx.x == 0) g_count = 0u;
}

extern "C" void kernel_launch(void* const* d_in, const int* in_sizes, int n_in,
                              void* d_out, int out_size)
{
    diar_loss_kernel<<<GRID, THREADS>>>(
        (const float*)d_in[0], (const float*)d_in[1],
        (const float*)d_in[2], (const float*)d_in[3],
        (const int*)d_in[4], (float*)d_out);
}

// round 6
// speedup vs baseline: 1.1215x; 1.1215x over previous
#include <cuda_runtime.h>

// DiarizationLoss: B=32, T=65536, S=4, scalar output. Single fused kernel.

#define NB 32
#define NT 65536
#define CEPS 1e-7f
#define LN2F 0.69314718055994531f

#define CHUNKS 16
#define THREADS 256
#define CHUNK_T (NT / CHUNKS)              // 4096
#define GROUPS (CHUNK_T / (THREADS * 4))   // 4 groups of 4 elements per thread
#define GRID (NB * CHUNKS)                 // 512 blocks -> single wave @3/SM

__device__ float g_part[NB][21];
__device__ unsigned int g_count;

// lengths dtype probe: values in [32768,65536), nonzero.
// int64 LE => word1 (hi of lengths[0]) == 0 ; int32 => word1 >= 32768.
__device__ __forceinline__ int load_len(const int* __restrict__ p32, int b) {
    return (p32[1] == 0) ? p32[2 * b] : p32[b];
}

__global__ __launch_bounds__(THREADS, 3) void diar_loss_kernel(
    const float* __restrict__ ps,
    const float* __restrict__ pv,
    const float* __restrict__ lb,
    const float* __restrict__ vad,
    const int*   __restrict__ len32,
    float*       __restrict__ out)
{
    const int b     = blockIdx.x >> 4;           // / CHUNKS
    const int chunk = blockIdx.x & (CHUNKS - 1);
    const int len   = load_len(len32, b);
    const int t0    = chunk * CHUNK_T;

    if (t0 < len) {
        float acc[21];
        #pragma unroll
        for (int k = 0; k < 21; k++) acc[k] = 0.0f;

        const float4* __restrict__ psb  = (const float4*)(ps + (size_t)b * NT * 4);
        const float4* __restrict__ lbb  = (const float4*)(lb + (size_t)b * NT * 4);
        const float*  __restrict__ pvb  = pv  + (size_t)b * NT;
        const float*  __restrict__ vb   = vad + (size_t)b * NT;
        const float4* __restrict__ pv4b = (const float4*)pvb;
        const float4* __restrict__ v4b  = (const float4*)vb;

        // accumulate base-2 logs; multiply by ln2 in finalize
        auto elem = [&](float4 p4, float4 l4, float pvv, float v) {
            float pp[4] = {p4.x, p4.y, p4.z, p4.w};
            float ll[4] = {l4.x, l4.y, l4.z, l4.w};
            float d[4];
            #pragma unroll
            for (int i = 0; i < 4; i++) {
                float p  = fminf(fmaxf(pp[i], CEPS), 1.0f - CEPS);
                float lq = __log2f(1.0f - p);
                float lp = __log2f(p);
                d[i] = lp - lq;
                acc[16 + i] += lq;
            }
            #pragma unroll
            for (int i = 0; i < 4; i++)
                #pragma unroll
                for (int j = 0; j < 4; j++)
                    acc[i * 4 + j] += d[i] * ll[j];
            pvv = fminf(fmaxf(pvv, CEPS), 1.0f - CEPS);
            float arg = (v > 0.5f) ? pvv : (1.0f - pvv);
            acc[20] -= __log2f(arg);
        };

        if (t0 + CHUNK_T <= len) {
            // full chunk: 4-element groups, 10 independent LDG.128 per group
            #pragma unroll
            for (int g = 0; g < GROUPS; g++) {
                const int tg = t0 + 4 * threadIdx.x + g * (THREADS * 4);
                float4 P0 = psb[tg],     P1 = psb[tg + 1];
                float4 P2 = psb[tg + 2], P3 = psb[tg + 3];
                float4 L0 = lbb[tg],     L1 = lbb[tg + 1];
                float4 L2 = lbb[tg + 2], L3 = lbb[tg + 3];
                float4 pv4 = pv4b[tg >> 2];
                float4 v4  = v4b[tg >> 2];
                elem(P0, L0, pv4.x, v4.x);
                elem(P1, L1, pv4.y, v4.y);
                elem(P2, L2, pv4.z, v4.z);
                elem(P3, L3, pv4.w, v4.w);
            }
        } else {
            // boundary chunk: scalar-strided, per-element guard
            for (int t = t0 + threadIdx.x; t < len; t += THREADS)
                elem(psb[t], lbb[t], pvb[t], vb[t]);
        }

        // block reduction: warp shuffle -> shared -> one RED per value
        __shared__ float sm[21][8];
        const int lane = threadIdx.x & 31;
        const int w    = threadIdx.x >> 5;
        #pragma unroll
        for (int k = 0; k < 21; k++) {
            float v = acc[k];
            v += __shfl_down_sync(0xffffffffu, v, 16);
            v += __shfl_down_sync(0xffffffffu, v, 8);
            v += __shfl_down_sync(0xffffffffu, v, 4);
            v += __shfl_down_sync(0xffffffffu, v, 2);
            v += __shfl_down_sync(0xffffffffu, v, 1);
            if (lane == 0) sm[k][w] = v;
        }
        __syncthreads();
        if (threadIdx.x < 21) {
            float v = 0.0f;
            #pragma unroll
            for (int ww = 0; ww < 8; ww++) v += sm[threadIdx.x][ww];
            atomicAdd(&g_part[b][threadIdx.x], v);
        }
    }

    // ---- last-block finalize ----
    __shared__ int s_last;
    if (threadIdx.x == 0) {
        __threadfence();
        unsigned prev = atomicAdd(&g_count, 1u);
        s_last = (prev == (unsigned)(GRID - 1));
    }
    __syncthreads();
    if (!s_last) return;
    __threadfence();

    if (threadIdx.x < NB) {
        const int bb = threadIdx.x;
        const float msum = (float)load_len(len32, bb);
        const float scal = LN2F / msum;   // fold ln2 (base-2 logs) here

        float L[4][4];
        #pragma unroll
        for (int i = 0; i < 4; i++)
            #pragma unroll
            for (int j = 0; j < 4; j++)
                L[i][j] = -(g_part[bb][i * 4 + j] + g_part[bb][16 + i]) * scal;

        float best = 3.4e38f;
        #pragma unroll
        for (int a = 0; a < 4; a++)
            #pragma unroll
            for (int cc = 0; cc < 4; cc++) {
                if (cc == a) continue;
                #pragma unroll
                for (int e = 0; e < 4; e++) {
                    if (e == a || e == cc) continue;
                    int f = 6 - a - cc - e;
                    best = fminf(best, L[0][a] + L[1][cc] + L[2][e] + L[3][f]);
                }
            }
        best *= 0.25f;

        float sb = best, sv = g_part[bb][20] * LN2F, sd = msum;
        #pragma unroll
        for (int off = 16; off >= 1; off >>= 1) {
            sb += __shfl_xor_sync(0xffffffffu, sb, off);
            sv += __shfl_xor_sync(0xffffffffu, sv, off);
            sd += __shfl_xor_sync(0xffffffffu, sd, off);
        }
        if (bb == 0)
            out[0] = (sb / (float)NB) + 0.5f * (sv / sd);
    }
    __syncthreads();

    // reset scratch for next graph replay
    for (int i = threadIdx.x; i < NB * 21; i += THREADS)
        ((float*)g_part)[i] = 0.0f;
    if (threadIdx.x == 0) g_count = 0u;
}

extern "C" void kernel_launch(void* const* d_in, const int* in_sizes, int n_in,
                              void* d_out, int out_size)
{
    diar_loss_kernel<<<GRID, THREADS>>>(
        (const float*)d_in[0], (const float*)d_in[1],
        (const float*)d_in[2], (const float*)d_in[3],
        (const int*)d_in[4], (float*)d_out);
}